// round 5
// baseline (speedup 1.0000x reference)
#include <cuda_runtime.h>
#include <math.h>
#include <stdint.h>

// ---------------------------------------------------------------------------
// GDER: out[b] = mean( Rx^2 + Ry^2 ) over valid 498x498 map.
// sum(Gy) is cancellation noise => Gy/sum(Gy) taps ~1e15 and Ry^2 dominates by
// >1e16 relative. Only the Gy path is computed, as a separable conv
// Gy = A(y)*B(x), 1/sum(Gy) folded into vertical taps. sum(Gy) replicated on
// host in numpy's exact f64 pairwise order (validated R1-R4: rel_err ~8.7e-8).
//
// R5: L1/smem traffic attack. 2 output rows per iteration; each thread does
// horizontal for 4 packed outputs from one 18-u64 window (36B smem-read per
// packed output vs 64B before). Barriers halved (1 per 2 rows). Vertical ring
// stays 15 slots via insert-between-rows schedule.
// ---------------------------------------------------------------------------

#define NB        64
#define W         512
#define OUTW      498
#define TILE_ROWS 30
#define ITERS     15      // 2 rows per iteration
#define TILES_Y   17      // 17*30 = 510 >= 498

typedef unsigned long long u64;

struct Weights {
    float hw[8];   // horizontal symmetric taps: hw[0..6] pair weights, hw[7] center
    float vw[7];   // vertical antisymmetric taps (scaled by 1/sum(Gy))
};

__device__ double g_partials[NB * TILES_Y];
__device__ int    g_count[NB];   // zero-initialized; self-resetting

// ---- f32x2 packed helpers (sm_100+) ----
__device__ __forceinline__ u64 pack2(float lo, float hi) {
    u64 r; asm("mov.b64 %0, {%1, %2};" : "=l"(r) : "f"(lo), "f"(hi)); return r;
}
__device__ __forceinline__ void unpack2(u64 v, float& lo, float& hi) {
    asm("mov.b64 {%0, %1}, %2;" : "=f"(lo), "=f"(hi) : "l"(v));
}
__device__ __forceinline__ u64 fma2(u64 a, u64 b, u64 c) {
    u64 d; asm("fma.rn.f32x2 %0, %1, %2, %3;" : "=l"(d) : "l"(a), "l"(b), "l"(c)); return d;
}
__device__ __forceinline__ u64 add2(u64 a, u64 b) {
    u64 d; asm("add.rn.f32x2 %0, %1, %2;" : "=l"(d) : "l"(a), "l"(b)); return d;
}
__device__ __forceinline__ u64 neg2(u64 a) { return a ^ 0x8000000080000000ull; }

__global__ __launch_bounds__(128, 4) void gder_kernel(const float* __restrict__ x,
                                                      Weights wt,
                                                      float* __restrict__ out)
{
    const int t     = threadIdx.x;
    const int tileY = blockIdx.x;
    const int b     = blockIdx.y;
    const int y0    = tileY * TILE_ROWS;
    const float* __restrict__ img = x + (size_t)b * W * W;

    // vertical results, double-buffered sets x 2 rows; idx 256..269 = extension
    __shared__ __align__(16) u64 vbuf[2][2][272];
    __shared__ double red[128];

    // packed weights (symmetric horizontal taps share 8 regs)
    u64 hw2[8], vp[7];
    #pragma unroll
    for (int j = 0; j < 8; ++j) hw2[j] = pack2(wt.hw[j], wt.hw[j]);
    #pragma unroll
    for (int k = 0; k < 7; ++k) vp[k] = pack2(wt.vw[k], wt.vw[k]);

    const int c  = 2 * t;          // vertical stream u64 indices c, c+1
    const int half = t >> 6;       // which of the 2 rows this thread filters
    const int cw = 4 * (t & 63);   // horizontal window base (u64 idx), 4 outputs

    const float* __restrict__ pL = img + c;
    const float* __restrict__ pR = img + c + 256;

    // register ring: 15 rows x 2 packed streams
    u64 h0[15], h1[15];
    #pragma unroll
    for (int i = 0; i < 14; ++i) {
        const float2 L = *reinterpret_cast<const float2*>(pL + (size_t)(y0 + i) * W);
        const float2 R = *reinterpret_cast<const float2*>(pR + (size_t)(y0 + i) * W);
        h0[i] = pack2(L.x, R.x);
        h1[i] = pack2(L.y, R.y);
    }
    // prefetch rows y0+14, y0+15 (always valid: y0 <= 480)
    float2 pfAL = *reinterpret_cast<const float2*>(pL + (size_t)(y0 + 14) * W);
    float2 pfAR = *reinterpret_cast<const float2*>(pR + (size_t)(y0 + 14) * W);
    float2 pfBL = *reinterpret_cast<const float2*>(pL + (size_t)(y0 + 15) * W);
    float2 pfBR = *reinterpret_cast<const float2*>(pR + (size_t)(y0 + 15) * W);

    u64 facc = 0ull;

    #pragma unroll
    for (int i = 0; i < ITERS; ++i) {
        const int set = i & 1;

        // insert row R+14 into ring (R = y0 + 2i)
        h0[(14 + 2 * i) % 15] = pack2(pfAL.x, pfAR.x);
        h1[(14 + 2 * i) % 15] = pack2(pfAL.y, pfAR.y);

        // vertical for row R: uses ring rows R..R+14
        u64 sR0, sR1;
        {
            u64 a0 = 0ull, b0 = 0ull, a1 = 0ull, b1 = 0ull;
            #pragma unroll
            for (int k = 0; k < 7; ++k) {
                a0 = fma2(vp[k], h0[(2 * i + k) % 15], a0);
                b0 = fma2(vp[k], h0[(2 * i + 14 - k) % 15], b0);
                a1 = fma2(vp[k], h1[(2 * i + k) % 15], a1);
                b1 = fma2(vp[k], h1[(2 * i + 14 - k) % 15], b1);
            }
            sR0 = add2(a0, neg2(b0));
            sR1 = add2(a1, neg2(b1));
        }

        // insert row R+15 over the oldest slot (row R, no longer needed)
        h0[(2 * i) % 15] = pack2(pfBL.x, pfBR.x);
        h1[(2 * i) % 15] = pack2(pfBL.y, pfBR.y);

        // prefetch rows R+16, R+17 (clamped; clamped rows feed only
        // discarded output rows >= 498)
        {
            int gA = y0 + 2 * i + 16; gA = gA < (W - 1) ? gA : (W - 1);
            int gB = y0 + 2 * i + 17; gB = gB < (W - 1) ? gB : (W - 1);
            pfAL = *reinterpret_cast<const float2*>(pL + (size_t)gA * W);
            pfAR = *reinterpret_cast<const float2*>(pR + (size_t)gA * W);
            pfBL = *reinterpret_cast<const float2*>(pL + (size_t)gB * W);
            pfBR = *reinterpret_cast<const float2*>(pR + (size_t)gB * W);
        }

        // vertical for row R+1: uses ring rows R+1..R+15
        u64 sS0, sS1;
        {
            u64 a0 = 0ull, b0 = 0ull, a1 = 0ull, b1 = 0ull;
            #pragma unroll
            for (int k = 0; k < 7; ++k) {
                a0 = fma2(vp[k], h0[(2 * i + 1 + k) % 15], a0);
                b0 = fma2(vp[k], h0[(2 * i + 15 - k) % 15], b0);
                a1 = fma2(vp[k], h1[(2 * i + 1 + k) % 15], a1);
                b1 = fma2(vp[k], h1[(2 * i + 15 - k) % 15], b1);
            }
            sS0 = add2(a0, neg2(b0));
            sS1 = add2(a1, neg2(b1));
        }

        // stage both rows' vertical results
        *reinterpret_cast<ulonglong2*>(&vbuf[set][0][c]) = make_ulonglong2(sR0, sR1);
        *reinterpret_cast<ulonglong2*>(&vbuf[set][1][c]) = make_ulonglong2(sS0, sS1);
        if (t < 7) {   // right-edge extension: (hi lane value, 0), idx 256..269
            float lo, hiR0, hiR1, hiS0, hiS1;
            unpack2(sR0, lo, hiR0);
            unpack2(sR1, lo, hiR1);
            unpack2(sS0, lo, hiS0);
            unpack2(sS1, lo, hiS1);
            vbuf[set][0][256 + c]     = pack2(hiR0, 0.f);
            vbuf[set][0][256 + c + 1] = pack2(hiR1, 0.f);
            vbuf[set][1][256 + c]     = pack2(hiS0, 0.f);
            vbuf[set][1][256 + c + 1] = pack2(hiS1, 0.f);
        }
        __syncthreads();   // one barrier per 2 rows (double-buffered sets)

        // horizontal: 4 packed outputs (cw..cw+3) on row (y0 + 2i + half)
        // from window u64 idx cw..cw+17, streamed via 9 LDS.128.
        if (y0 + 2 * i + half < OUTW) {
            u64 o[4] = {0ull, 0ull, 0ull, 0ull};
            #pragma unroll
            for (int q = 0; q < 9; ++q) {
                const ulonglong2 v2 =
                    *reinterpret_cast<const ulonglong2*>(&vbuf[set][half][cw + 2 * q]);
                #pragma unroll
                for (int e = 0; e < 2; ++e) {
                    const u64 v = e ? v2.y : v2.x;
                    const int wq = 2 * q + e;
                    #pragma unroll
                    for (int m = 0; m < 4; ++m) {
                        const int j = wq - m;
                        if (j >= 0 && j <= 14)
                            o[m] = fma2(hw2[j < 8 ? j : 14 - j], v, o[m]);
                    }
                }
            }
            #pragma unroll
            for (int m = 0; m < 4; ++m) {
                // hi lane = output col cw+m+256, invalid beyond 497
                u64 om = o[m];
                if (cw + m > 241) om &= 0x00000000FFFFFFFFull;
                facc = fma2(om, om, facc);
            }
        }
    }

    // deterministic block reduction in double
    {
        float flo, fhi;
        unpack2(facc, flo, fhi);
        red[t] = (double)flo + (double)fhi;
    }
    __syncthreads();
    #pragma unroll
    for (int s = 64; s > 0; s >>= 1) {
        if (t < s) red[t] += red[t + s];
        __syncthreads();
    }
    if (t == 0) {
        g_partials[b * TILES_Y + tileY] = red[0];
        __threadfence();
        const int old = atomicAdd(&g_count[b], 1);
        if (old == TILES_Y - 1) {   // last block for this batch: fixed-order final sum
            __threadfence();
            double s = 0.0;
            #pragma unroll
            for (int i = 0; i < TILES_Y; ++i)
                s += __ldcg(&g_partials[b * TILES_Y + i]);
            out[b] = (float)(s * (1.0 / ((double)OUTW * (double)OUTW)));
            g_count[b] = 0;         // reset for next graph replay
        }
    }
}

// ---------------------------------------------------------------------------
// Host side: replicate numpy float64 semantics exactly (validated R1-R4).
// ---------------------------------------------------------------------------

// numpy's pairwise_sum for contiguous float64 (PW_BLOCKSIZE = 128)
static double np_pairwise(const double* a, int n)
{
    if (n < 8) {
        double res = 0.0;
        for (int i = 0; i < n; ++i) res += a[i];
        return res;
    }
    else if (n <= 128) {
        double r[8];
        for (int j = 0; j < 8; ++j) r[j] = a[j];
        int i;
        for (i = 8; i < n - (n % 8); i += 8)
            for (int j = 0; j < 8; ++j) r[j] += a[i + j];
        double res = ((r[0] + r[1]) + (r[2] + r[3])) + ((r[4] + r[5]) + (r[6] + r[7]));
        for (; i < n; ++i) res += a[i];
        return res;
    }
    else {
        int n2 = n / 2;
        n2 -= n2 % 8;
        return np_pairwise(a, n2) + np_pairwise(a + n2, n - n2);
    }
}

extern "C" void kernel_launch(void* const* d_in, const int* in_sizes, int n_in,
                              void* d_out, int out_size)
{
    (void)in_sizes; (void)n_in; (void)out_size;
    const float* x  = (const float*)d_in[0];
    float*      out = (float*)d_out;

    const double sig     = 7.0 / 2.5;              // N=15//2=7; sig = N/2.5
    const double sig2    = pow(sig, 2.0);          // sig ** 2 (CPython float_pow -> libm pow)
    const double twosig2 = 2.0 * sig2;
    const double denomG  = (2.0 * M_PI) * sig;

    double Gy[225];
    for (int i = 0; i < 15; ++i) {
        const int yy = i - 7;
        for (int j = 0; j < 15; ++j) {
            const int xx = j - 7;
            const double G = exp((double)(-(xx * xx + yy * yy)) / twosig2) / denomG;
            Gy[i * 15 + j] = ((double)(-yy) * G) / sig2;
        }
    }
    const double s = np_pairwise(Gy, 225);         // np.sum(Gy), numpy pairwise order

    Weights wt;
    for (int j = 0; j < 8; ++j) {
        const int xx = j - 7;
        wt.hw[j] = (float)(exp((double)(-(xx * xx)) / twosig2) / denomG);
    }
    for (int k = 0; k < 7; ++k) {
        const int yy = k - 7;
        const double A = (((double)(-yy) * exp((double)(-(yy * yy)) / twosig2)) / sig2) / s;
        wt.vw[k] = (float)A;
    }

    dim3 grid(TILES_Y, NB);
    gder_kernel<<<grid, 128>>>(x, wt, out);
}

// round 6
// speedup vs baseline: 1.1111x; 1.1111x over previous
#include <cuda_runtime.h>
#include <math.h>
#include <stdint.h>

// ---------------------------------------------------------------------------
// GDER: out[b] = mean( Rx^2 + Ry^2 ) over valid 498x498 map.
// sum(Gy) is cancellation noise => Gy/sum(Gy) taps ~1e15 and Ry^2 dominates by
// >1e16 relative. Only the Gy path is computed, as a separable conv
// Gy = A(y)*B(x), 1/sum(Gy) folded into vertical taps. sum(Gy) replicated on
// host in numpy's exact f64 pairwise order (validated R1-R5, rel_err ~8.7e-8).
//
// R6: R4 structure (TILE=30, 1 barrier/row, 8-LDS horizontal window) +
// DISTANCE-2 prefetch: the global load issued at row r is consumed at row
// r+2 (~300cyc cover vs L2-hit 234-262cyc), so ring-insert no longer stalls.
// Sign-flip via XOR (ALU) instead of a packed -1 register.
// ---------------------------------------------------------------------------

#define NB        64
#define W         512
#define OUTW      498
#define TILE_ROWS 30
#define TILES_Y   17      // 17*30 = 510 >= 498

typedef unsigned long long u64;

struct Weights {
    float hw[8];   // horizontal symmetric taps: hw[0..6] pair weights, hw[7] center
    float vw[7];   // vertical antisymmetric taps (scaled by 1/sum(Gy))
};

__device__ double g_partials[NB * TILES_Y];
__device__ int    g_count[NB];   // zero-initialized; self-resetting

// ---- f32x2 packed helpers (sm_100+) ----
__device__ __forceinline__ u64 pack2(float lo, float hi) {
    u64 r; asm("mov.b64 %0, {%1, %2};" : "=l"(r) : "f"(lo), "f"(hi)); return r;
}
__device__ __forceinline__ void unpack2(u64 v, float& lo, float& hi) {
    asm("mov.b64 {%0, %1}, %2;" : "=f"(lo), "=f"(hi) : "l"(v));
}
__device__ __forceinline__ u64 fma2(u64 a, u64 b, u64 c) {
    u64 d; asm("fma.rn.f32x2 %0, %1, %2, %3;" : "=l"(d) : "l"(a), "l"(b), "l"(c)); return d;
}
__device__ __forceinline__ u64 add2(u64 a, u64 b) {
    u64 d; asm("add.rn.f32x2 %0, %1, %2;" : "=l"(d) : "l"(a), "l"(b)); return d;
}
__device__ __forceinline__ u64 mul2(u64 a, u64 b) {
    u64 d; asm("mul.rn.f32x2 %0, %1, %2;" : "=l"(d) : "l"(a), "l"(b)); return d;
}
__device__ __forceinline__ u64 neg2(u64 a) { return a ^ 0x8000000080000000ull; }

__global__ __launch_bounds__(128, 4) void gder_kernel(const float* __restrict__ x,
                                                      Weights wt,
                                                      float* __restrict__ out)
{
    const int t     = threadIdx.x;
    const int tileY = blockIdx.x;
    const int b     = blockIdx.y;
    const int y0    = tileY * TILE_ROWS;
    const float* __restrict__ img = x + (size_t)b * W * W;

    // vertical results, packed (v[i], v[i+256]); entries 256..269 written each
    // row by t<7 as (v[256+i], 0) for right-edge window wrap
    __shared__ __align__(16) u64 vbuf[2][272];
    __shared__ double red[128];

    // packed weights
    u64 hw2[8], vp[7];
    #pragma unroll
    for (int j = 0; j < 8; ++j) hw2[j] = pack2(wt.hw[j], wt.hw[j]);
    #pragma unroll
    for (int k = 0; k < 7; ++k) vp[k] = pack2(wt.vw[k], wt.vw[k]);

    const int c = 2 * t;   // packed stream indices c, c+1; lanes = (col, col+256)

    const float* __restrict__ pL = img + c;
    const float* __restrict__ pR = img + c + 256;

    // register ring: 15 rows x 2 packed streams
    u64 h0[15], h1[15];
    #pragma unroll
    for (int i = 0; i < 14; ++i) {
        const float2 L = *reinterpret_cast<const float2*>(pL + (size_t)(y0 + i) * W);
        const float2 R = *reinterpret_cast<const float2*>(pR + (size_t)(y0 + i) * W);
        h0[i] = pack2(L.x, R.x);
        h1[i] = pack2(L.y, R.y);
    }

    // distance-2 prefetch pipeline: pf0 = row y0+14 (consumed at row 0),
    // pf1 = row y0+15 (consumed at row 1). Both always valid (y0+15 <= 495).
    float2 pf0L = *reinterpret_cast<const float2*>(pL + (size_t)(y0 + 14) * W);
    float2 pf0R = *reinterpret_cast<const float2*>(pR + (size_t)(y0 + 14) * W);
    float2 pf1L = *reinterpret_cast<const float2*>(pL + (size_t)(y0 + 15) * W);
    float2 pf1R = *reinterpret_cast<const float2*>(pR + (size_t)(y0 + 15) * W);

    u64 facc = 0ull;
    int buf = 0;

    for (int g = 0; g < 2; ++g) {
        #pragma unroll
        for (int p = 0; p < 15; ++p) {
            const int r = 15 * g + p;          // row index within tile

            // consume pf0 (row y0+14+r) into ring slot (constant index per p)
            h0[(14 + p) % 15] = pack2(pf0L.x, pf0R.x);
            h1[(14 + p) % 15] = pack2(pf0L.y, pf0R.y);

            // rotate pipeline and issue the load consumed at row r+2.
            // Clamp to last row: clamped data reaches only discarded
            // output rows >= 498 (same argument as R4).
            pf0L = pf1L; pf0R = pf1R;
            {
                int gr = y0 + 16 + r;
                gr = gr < (W - 1) ? gr : (W - 1);
                pf1L = *reinterpret_cast<const float2*>(pL + (size_t)gr * W);
                pf1R = *reinterpret_cast<const float2*>(pR + (size_t)gr * W);
            }

            // vertical (antisymmetric): s = A - B via XOR sign flip + add2
            u64 a0 = 0ull, b0 = 0ull, a1 = 0ull, b1 = 0ull;
            #pragma unroll
            for (int k = 0; k < 7; ++k) {
                a0 = fma2(vp[k], h0[(p + k) % 15], a0);
                b0 = fma2(vp[k], h0[(p + 14 - k) % 15], b0);
                a1 = fma2(vp[k], h1[(p + k) % 15], a1);
                b1 = fma2(vp[k], h1[(p + 14 - k) % 15], b1);
            }
            const u64 s0 = add2(a0, neg2(b0));
            const u64 s1 = add2(a1, neg2(b1));

            *reinterpret_cast<ulonglong2*>(&vbuf[buf][c]) = make_ulonglong2(s0, s1);
            if (t < 7) {   // right-edge extension: (hi lane value, 0)
                float lo0, hi0, lo1, hi1;
                unpack2(s0, lo0, hi0);
                unpack2(s1, lo1, hi1);
                vbuf[buf][256 + c]     = pack2(hi0, 0.f);
                vbuf[buf][256 + c + 1] = pack2(hi1, 0.f);
            }
            __syncthreads();   // single barrier/row: double buffer covers WAR

            // horizontal (symmetric), packed, 2 packed outputs per thread
            if (y0 + r < OUTW) {
                u64 win[16];
                #pragma unroll
                for (int q = 0; q < 8; ++q) {
                    const ulonglong2 v2 =
                        *reinterpret_cast<const ulonglong2*>(&vbuf[buf][c + 2 * q]);
                    win[2 * q]     = v2.x;
                    win[2 * q + 1] = v2.y;
                }
                #pragma unroll
                for (int k = 0; k < 2; ++k) {
                    u64 o = mul2(hw2[7], win[k + 7]);
                    #pragma unroll
                    for (int j = 0; j < 7; ++j)
                        o = fma2(hw2[j], add2(win[k + j], win[k + 14 - j]), o);
                    // hi lane = output col 256+c+k; invalid beyond 497 (t > 120)
                    if (t > 120) o &= 0x00000000FFFFFFFFull;
                    facc = fma2(o, o, facc);
                }
            }
            buf ^= 1;
        }
    }

    // deterministic block reduction in double
    {
        float flo, fhi;
        unpack2(facc, flo, fhi);
        red[t] = (double)flo + (double)fhi;
    }
    __syncthreads();
    #pragma unroll
    for (int s = 64; s > 0; s >>= 1) {
        if (t < s) red[t] += red[t + s];
        __syncthreads();
    }
    if (t == 0) {
        g_partials[b * TILES_Y + tileY] = red[0];
        __threadfence();
        const int old = atomicAdd(&g_count[b], 1);
        if (old == TILES_Y - 1) {   // last block for this batch: fixed-order final sum
            __threadfence();
            double s = 0.0;
            #pragma unroll
            for (int i = 0; i < TILES_Y; ++i)
                s += __ldcg(&g_partials[b * TILES_Y + i]);
            out[b] = (float)(s * (1.0 / ((double)OUTW * (double)OUTW)));
            g_count[b] = 0;         // reset for next graph replay
        }
    }
}

// ---------------------------------------------------------------------------
// Host side: replicate numpy float64 semantics exactly (validated R1-R5).
// ---------------------------------------------------------------------------

// numpy's pairwise_sum for contiguous float64 (PW_BLOCKSIZE = 128)
static double np_pairwise(const double* a, int n)
{
    if (n < 8) {
        double res = 0.0;
        for (int i = 0; i < n; ++i) res += a[i];
        return res;
    }
    else if (n <= 128) {
        double r[8];
        for (int j = 0; j < 8; ++j) r[j] = a[j];
        int i;
        for (i = 8; i < n - (n % 8); i += 8)
            for (int j = 0; j < 8; ++j) r[j] += a[i + j];
        double res = ((r[0] + r[1]) + (r[2] + r[3])) + ((r[4] + r[5]) + (r[6] + r[7]));
        for (; i < n; ++i) res += a[i];
        return res;
    }
    else {
        int n2 = n / 2;
        n2 -= n2 % 8;
        return np_pairwise(a, n2) + np_pairwise(a + n2, n - n2);
    }
}

extern "C" void kernel_launch(void* const* d_in, const int* in_sizes, int n_in,
                              void* d_out, int out_size)
{
    (void)in_sizes; (void)n_in; (void)out_size;
    const float* x  = (const float*)d_in[0];
    float*      out = (float*)d_out;

    const double sig     = 7.0 / 2.5;              // N=15//2=7; sig = N/2.5
    const double sig2    = pow(sig, 2.0);          // sig ** 2 (CPython float_pow -> libm pow)
    const double twosig2 = 2.0 * sig2;
    const double denomG  = (2.0 * M_PI) * sig;

    double Gy[225];
    for (int i = 0; i < 15; ++i) {
        const int yy = i - 7;
        for (int j = 0; j < 15; ++j) {
            const int xx = j - 7;
            const double G = exp((double)(-(xx * xx + yy * yy)) / twosig2) / denomG;
            Gy[i * 15 + j] = ((double)(-yy) * G) / sig2;
        }
    }
    const double s = np_pairwise(Gy, 225);         // np.sum(Gy), numpy pairwise order

    Weights wt;
    for (int j = 0; j < 8; ++j) {
        const int xx = j - 7;
        wt.hw[j] = (float)(exp((double)(-(xx * xx)) / twosig2) / denomG);
    }
    for (int k = 0; k < 7; ++k) {
        const int yy = k - 7;
        const double A = (((double)(-yy) * exp((double)(-(yy * yy)) / twosig2)) / sig2) / s;
        wt.vw[k] = (float)A;
    }

    dim3 grid(TILES_Y, NB);
    gder_kernel<<<grid, 128>>>(x, wt, out);
}